// round 17
// baseline (speedup 1.0000x reference)
#include <cuda_runtime.h>
#include <cuda_bf16.h>
#include <cstdint>

#define BB 2
#define NQ 300
#define NT 300
#define QP 320
#define IH 256
#define IW 256
#define HW 65536
#define NP 12544
#define SPLITK 8
#define KSPLIT (NP/SPLITK)      // 1568
#define KSTAGE 32
#define NSTAGES (KSPLIT/KSTAGE) // 49

#define PSTRIDE 264             // pred smem row stride (elems), interior at col 4
#define PROWS4 66               // 1 guard + 65 interior rows (band 3: 64 + guard)

// ---------------- scratch ----------------
__device__ __nv_bfloat16 g_om[(size_t)BB*QP*NP];   // [b][q][i] permuted p-axis
__device__ __nv_bfloat16 g_s [(size_t)BB*QP*NP];
__device__ __nv_bfloat16 g_tm[(size_t)BB*QP*NP];
__device__ float2 g_ppts[(size_t)BB*NP];           // permuted point coords
__device__ int g_off[BB*5];                        // 4-band prefix offsets
__device__ float g_negP[4*BB*NQ];
__device__ float g_sP  [4*BB*NQ];
__device__ float g_tmsum[BB*NT];
__device__ float g_C1p[(size_t)SPLITK*BB*NQ*NT];
__device__ float g_C2p[(size_t)SPLITK*BB*NQ*NT];

static __device__ __forceinline__ uint32_t smem_u32(const void* p) {
    return (uint32_t)__cvta_generic_to_shared(p);
}
static __device__ __forceinline__ void cpasync16(uint32_t dst, const void* src) {
    asm volatile("cp.async.cg.shared.global [%0], [%1], 16;\n" :: "r"(dst), "l"(src));
}
static __device__ __forceinline__ void cp_commit() { asm volatile("cp.async.commit_group;\n"); }
template<int N> static __device__ __forceinline__ void cp_wait() {
    asm volatile("cp.async.wait_group %0;\n" :: "n"(N));
}
static __device__ __forceinline__ float warp_sum(float v) {
    #pragma unroll
    for (int o = 16; o > 0; o >>= 1) v += __shfl_xor_sync(0xffffffffu, v, o);
    return v;
}
static __device__ __forceinline__ int warp_sum_i(int v) {
    #pragma unroll
    for (int o = 16; o > 0; o >>= 1) v += __shfl_xor_sync(0xffffffffu, v, o);
    return v;
}

// ---------- K0: 4-way partition of point coords by y-band (deterministic) ----
__global__ __launch_bounds__(1024) void k_build(const float* __restrict__ pts) {
    __shared__ int warpCnt[4][32], warpOff[4][32];
    __shared__ int curs[4], chunkTot[4], tot[4];
    int b = blockIdx.x;
    int tid = threadIdx.x, warp = tid >> 5, lane = tid & 31;
    uint32_t lt = (1u << lane) - 1u;

    const float2* pp = ((const float2*)pts) + (size_t)b*NP;
    float2* dst = g_ppts + (size_t)b*NP;

    if (tid < 4) tot[tid] = 0;
    __syncthreads();

    // pass 1: band totals (int atomics -> deterministic)
    {
        int cnt[4] = {0,0,0,0};
        for (int p = tid; p < NP; p += 1024) {
            float y = fmaf(pp[p].y, (float)IH, -0.5f);
            int iy0 = (int)floorf(y);
            int band = min(max(iy0, 0), 255) >> 6;
            cnt[band]++;
        }
        #pragma unroll
        for (int g = 0; g < 4; g++) {
            int s = warp_sum_i(cnt[g]);
            if (lane == 0 && s) atomicAdd(&tot[g], s);
        }
    }
    __syncthreads();
    if (tid == 0) {
        int base = 0;
        g_off[b*5 + 0] = 0;
        #pragma unroll
        for (int g = 0; g < 4; g++) {
            curs[g] = base;
            base += tot[g];
            g_off[b*5 + g + 1] = base;
        }
    }
    __syncthreads();

    // pass 2: deterministic scatter
    for (int c0 = 0; c0 < NP; c0 += 1024) {
        int p = c0 + tid;
        bool active = p < NP;
        float2 pc = {0.f, 0.f};
        int band = -1;
        if (active) {
            pc = pp[p];
            float y = fmaf(pc.y, (float)IH, -0.5f);
            int iy0 = (int)floorf(y);
            band = min(max(iy0, 0), 255) >> 6;
        }
        uint32_t mg[4];
        #pragma unroll
        for (int g = 0; g < 4; g++)
            mg[g] = __ballot_sync(0xffffffffu, band == g);
        if (lane == 0) {
            #pragma unroll
            for (int g = 0; g < 4; g++) warpCnt[g][warp] = __popc(mg[g]);
        }
        __syncthreads();
        if (warp == 0) {
            #pragma unroll
            for (int g = 0; g < 4; g++) {
                int v = warpCnt[g][lane], c = v;
                #pragma unroll
                for (int o = 1; o < 32; o <<= 1) {
                    int t = __shfl_up_sync(0xffffffffu, v, o);
                    if (lane >= o) v += t;
                }
                warpOff[g][lane] = v - c;
                if (lane == 31) chunkTot[g] = v;
            }
        }
        __syncthreads();
        if (active) {
            int pre = __popc(mg[band] & lt);
            int idx = curs[band] + warpOff[band][warp] + pre;
            dst[idx] = pc;
        }
        __syncthreads();
        if (tid == 0) {
            #pragma unroll
            for (int g = 0; g < 4; g++) curs[g] += chunkTot[g];
        }
        __syncthreads();
    }
}

// ---------- K1a: pred sampler, quarter-band smem tile, 4 CTAs/SM -------------
__global__ __launch_bounds__(512, 4)
void k_sample_pred(const float* __restrict__ pred) {
    __shared__ __nv_bfloat16 smask[PROWS4*PSTRIDE];   // 66 x 264 = 34.8KB
    __shared__ float rbuf[32];
    int q = blockIdx.x, b = blockIdx.y, k = blockIdx.z;
    int tid = threadIdx.x, warp = tid >> 5, lane = tid & 31;

    // zero guards: row 0; row 65 if band 3; col guards 3 & 260 for all rows
    for (int c = tid; c < PSTRIDE; c += 512) smask[c] = __float2bfloat16(0.f);
    if (k == 3) for (int c = tid; c < PSTRIDE; c += 512)
        smask[65*PSTRIDE + c] = __float2bfloat16(0.f);
    if (tid < PROWS4*2) {
        int rr = tid >> 1, cc = (tid & 1) ? 260 : 3;
        smask[rr*PSTRIDE + cc] = __float2bfloat16(0.f);
    }

    // load mask rows [64k .. min(64k+64, 255)] into smem rows 1..nrows
    int nrows = (k < 3) ? 65 : 64;
    const float* src = pred + ((size_t)(b*NQ + q))*HW + (size_t)k*64*IW;
    int n4 = nrows * 64;
    for (int i = tid; i < n4; i += 512) {
        int r = i >> 6, c4 = i & 63;
        float4 v = ((const float4*)src)[(size_t)r*64 + c4];
        __nv_bfloat162 p0 = __floats2bfloat162_rn(v.x, v.y);
        __nv_bfloat162 p1 = __floats2bfloat162_rn(v.z, v.w);
        uint2 u; u.x = *(uint32_t*)&p0; u.y = *(uint32_t*)&p1;
        *(uint2*)&smask[(1 + r)*PSTRIDE + 4 + c4*4] = u;
    }
    __syncthreads();

    int start = g_off[b*5 + k];
    int end   = g_off[b*5 + k + 1];
    int rowadj = 1 - k*64;                 // smem row = iy0 + rowadj
    const float2* pp = g_ppts + (size_t)b*NP;
    size_t obase = ((size_t)(b*QP + q))*NP;
    float accA = 0.f, accB = 0.f;

    for (int i = start + tid; i < end; i += 512) {
        float2 pc = pp[i];
        float x = fmaf(pc.x, (float)IW, -0.5f);
        float y = fmaf(pc.y, (float)IH, -0.5f);
        float x0f = floorf(x), y0f = floorf(y);
        float wx = x - x0f, wy = y - y0f;
        int ix0 = (int)x0f, iy0 = (int)y0f;
        int a = (iy0 + rowadj)*PSTRIDE + ix0 + 4;
        float m00 = __bfloat162float(smask[a]);
        float m01 = __bfloat162float(smask[a + 1]);
        float m10 = __bfloat162float(smask[a + PSTRIDE]);
        float m11 = __bfloat162float(smask[a + PSTRIDE + 1]);
        float omx = 1.f - wx, omy = 1.f - wy;
        float v = omy*(omx*m00 + wx*m01) + wy*(omx*m10 + wx*m11);
        float e = __expf(-fabsf(v));
        float t = 1.f + e;
        float inv = __fdividef(1.f, t);
        float s = (v >= 0.f) ? inv : e * inv;
        float sp = fmaxf(v, 0.f) + __logf(t);
        accA += sp; accB += s;
        g_om[obase + i] = __float2bfloat16(v);
        g_s [obase + i] = __float2bfloat16(s);
    }

    accA = warp_sum(accA);
    accB = warp_sum(accB);
    if (lane == 0) { rbuf[warp] = accA; rbuf[16 + warp] = accB; }
    __syncthreads();
    if (warp == 0 && lane < 16) {
        float a = rbuf[lane];
        float bs = rbuf[16 + lane];
        #pragma unroll
        for (int o = 8; o > 0; o >>= 1) {
            a  += __shfl_xor_sync(0xffffu, a, o);
            bs += __shfl_xor_sync(0xffffu, bs, o);
        }
        if (lane == 0) {
            g_negP[k*BB*NQ + b*NQ + q] = a;
            g_sP  [k*BB*NQ + b*NQ + q] = bs;
        }
    }
}

// ---------- K1b: tgt sampler, guarded bit-mask + funnel-shift (R15) ----------
__global__ __launch_bounds__(512, 4)
void k_sample_tgt(const float* __restrict__ tgt) {
    __shared__ uint32_t sbits[2580];
    __shared__ float rbuf[16];
    int q = blockIdx.x, b = blockIdx.y;
    int tid = threadIdx.x, warp = tid >> 5, lane = tid & 31;

    for (int i = tid; i < 2580; i += 512) sbits[i] = 0;
    __syncthreads();

    const float* src = tgt + ((size_t)(b*NT + q))*HW;
    const float4* s4 = (const float4*)src;
    #pragma unroll 4
    for (int g = warp; g < HW/128; g += 16) {
        float4 v = s4[g*32 + lane];
        uint32_t nib = (v.x != 0.f ? 1u : 0u) | (v.y != 0.f ? 2u : 0u)
                     | (v.z != 0.f ? 4u : 0u) | (v.w != 0.f ? 8u : 0u);
        uint32_t word = nib << ((lane & 7)*4);
        word |= __shfl_xor_sync(0xffffffffu, word, 1);
        word |= __shfl_xor_sync(0xffffffffu, word, 2);
        word |= __shfl_xor_sync(0xffffffffu, word, 4);
        if ((lane & 7) == 0) {
            int row = g >> 1;
            sbits[(row + 1)*10 + 1 + (g & 1)*4 + (lane >> 3)] = word;
        }
    }
    __syncthreads();

    const float2* pp = g_ppts + (size_t)b*NP;
    size_t obase = ((size_t)(b*QP + q))*NP;
    float acc = 0.f;

    for (int i = tid; i < NP; i += 512) {
        float2 pc = pp[i];
        float x = fmaf(pc.x, (float)IW, -0.5f);
        float y = fmaf(pc.y, (float)IH, -0.5f);
        float x0f = floorf(x), y0f = floorf(y);
        float wx = x - x0f, wy = y - y0f;
        int ix0 = (int)x0f, iy0 = (int)y0f;
        int wi = (iy0 + 1)*10 + 1 + (ix0 >> 5);
        int bit = ix0 & 31;
        uint32_t p0 = __funnelshift_r(sbits[wi],      sbits[wi + 1],  bit) & 3u;
        uint32_t p1 = __funnelshift_r(sbits[wi + 10], sbits[wi + 11], bit) & 3u;
        float b00 = (float)(p0 & 1u), b01 = (float)(p0 >> 1);
        float b10 = (float)(p1 & 1u), b11 = (float)(p1 >> 1);
        float omx = 1.f - wx, omy = 1.f - wy;
        float v = omy*(omx*b00 + wx*b01) + wy*(omx*b10 + wx*b11);
        acc += v;
        g_tm[obase + i] = __float2bfloat16(v);
    }

    acc = warp_sum(acc);
    if (lane == 0) rbuf[warp] = acc;
    __syncthreads();
    if (warp == 0 && lane < 16) {
        float a = rbuf[lane];
        #pragma unroll
        for (int o = 8; o > 0; o >>= 1) a += __shfl_xor_sync(0xffffu, a, o);
        if (lane == 0) g_tmsum[b*NT + q] = a;
    }
}

// ---------------- K2: dual bf16 GEMM, split-K 8, 3-stage ring (R8 config) ----
__device__ __forceinline__ void ldsm4(uint32_t* r, uint32_t addr) {
    asm volatile("ldmatrix.sync.aligned.m8n8.x4.shared.b16 {%0,%1,%2,%3}, [%4];"
        : "=r"(r[0]), "=r"(r[1]), "=r"(r[2]), "=r"(r[3]) : "r"(addr));
}
__device__ __forceinline__ void mma16816(float* d, const uint32_t* a, uint32_t b0, uint32_t b1) {
    asm volatile("mma.sync.aligned.m16n8k16.row.col.f32.bf16.bf16.f32 "
        "{%0,%1,%2,%3}, {%4,%5,%6,%7}, {%8,%9}, {%0,%1,%2,%3};"
        : "+f"(d[0]), "+f"(d[1]), "+f"(d[2]), "+f"(d[3])
        : "r"(a[0]), "r"(a[1]), "r"(a[2]), "r"(a[3]), "r"(b0), "r"(b1));
}

#define TPAD 40
#define TILE (64*TPAD)

__global__ __launch_bounds__(128) void k_gemm() {
    __shared__ __nv_bfloat16 sbuf[3][3][TILE];
    int m0 = blockIdx.x * 64, n0 = blockIdx.y * 64;
    int b = blockIdx.z >> 3, sk = blockIdx.z & 7;
    int kbeg = sk * KSPLIT;
    int tid = threadIdx.x, warp = tid >> 5, lane = tid & 31;
    int wm = (warp & 1) * 32, wn = (warp >> 1) * 32;

    const __nv_bfloat16* gA1 = g_om + (size_t)b*QP*NP;
    const __nv_bfloat16* gA2 = g_s  + (size_t)b*QP*NP;
    const __nv_bfloat16* gB  = g_tm + (size_t)b*QP*NP;

    int lrow = tid >> 2, lcol = (tid & 3) * 8;

    auto load_stage = [&](int buf, int k0) {
        #pragma unroll
        for (int it = 0; it < 2; it++) {
            int row = lrow + it*32;
            uint32_t d1 = smem_u32(&sbuf[buf][0][row*TPAD + lcol]);
            uint32_t d2 = smem_u32(&sbuf[buf][1][row*TPAD + lcol]);
            uint32_t d3 = smem_u32(&sbuf[buf][2][row*TPAD + lcol]);
            cpasync16(d1, gA1 + (size_t)(m0 + row)*NP + k0 + lcol);
            cpasync16(d2, gA2 + (size_t)(m0 + row)*NP + k0 + lcol);
            cpasync16(d3, gB  + (size_t)(n0 + row)*NP + k0 + lcol);
        }
    };

    float d1[2][4][4], d2[2][4][4];
    #pragma unroll
    for (int mi = 0; mi < 2; mi++)
        #pragma unroll
        for (int nj = 0; nj < 4; nj++)
            #pragma unroll
            for (int e = 0; e < 4; e++) { d1[mi][nj][e] = 0.f; d2[mi][nj][e] = 0.f; }

    int a_r = lane & 15, a_c = ((lane >> 4) & 1) * 8;
    int b_r = (lane & 7) + (((lane & 16) ? 8 : 0)), b_c = ((lane & 8) ? 8 : 0);

    load_stage(0, kbeg);            cp_commit();
    load_stage(1, kbeg + KSTAGE);   cp_commit();

    for (int s = 0; s < NSTAGES; s++) {
        if (s + 1 < NSTAGES) cp_wait<1>(); else cp_wait<0>();
        __syncthreads();
        if (s + 2 < NSTAGES) {
            load_stage((s + 2) % 3, kbeg + (s + 2)*KSTAGE);
            cp_commit();
        }

        int cur = s % 3;
        const __nv_bfloat16* t1 = sbuf[cur][0];
        const __nv_bfloat16* t2 = sbuf[cur][1];
        const __nv_bfloat16* tB = sbuf[cur][2];
        #pragma unroll
        for (int kk = 0; kk < 2; kk++) {
            uint32_t ao[2][4], as_[2][4], bf[2][4];
            #pragma unroll
            for (int mi = 0; mi < 2; mi++) {
                uint32_t off = (uint32_t)((wm + mi*16 + a_r)*TPAD + kk*16 + a_c)*2;
                ldsm4(ao[mi],  smem_u32(t1) + off);
                ldsm4(as_[mi], smem_u32(t2) + off);
            }
            #pragma unroll
            for (int nb = 0; nb < 2; nb++) {
                uint32_t off = (uint32_t)((wn + nb*16 + b_r)*TPAD + kk*16 + b_c)*2;
                ldsm4(bf[nb], smem_u32(tB) + off);
            }
            #pragma unroll
            for (int mi = 0; mi < 2; mi++)
                #pragma unroll
                for (int nj = 0; nj < 4; nj++) {
                    uint32_t b0 = bf[nj >> 1][(nj & 1)*2], b1 = bf[nj >> 1][(nj & 1)*2 + 1];
                    mma16816(d1[mi][nj], ao[mi],  b0, b1);
                    mma16816(d2[mi][nj], as_[mi], b0, b1);
                }
        }
    }

    float* C1 = g_C1p + (size_t)(sk*BB + b)*NQ*NT;
    float* C2 = g_C2p + (size_t)(sk*BB + b)*NQ*NT;
    int r = lane >> 2, c2 = (lane & 3)*2;
    #pragma unroll
    for (int mi = 0; mi < 2; mi++)
        #pragma unroll
        for (int nj = 0; nj < 4; nj++) {
            int m = m0 + wm + mi*16 + r;
            int n = n0 + wn + nj*8 + c2;
            if (m < NQ) {
                if (n     < NT) { C1[(size_t)m*NT + n]     = d1[mi][nj][0]; C2[(size_t)m*NT + n]     = d2[mi][nj][0]; }
                if (n + 1 < NT) { C1[(size_t)m*NT + n + 1] = d1[mi][nj][1]; C2[(size_t)m*NT + n + 1] = d2[mi][nj][1]; }
            }
            if (m + 8 < NQ) {
                if (n     < NT) { C1[(size_t)(m+8)*NT + n]     = d1[mi][nj][2]; C2[(size_t)(m+8)*NT + n]     = d2[mi][nj][2]; }
                if (n + 1 < NT) { C1[(size_t)(m+8)*NT + n + 1] = d1[mi][nj][3]; C2[(size_t)(m+8)*NT + n + 1] = d2[mi][nj][3]; }
            }
        }
}

// ---------------- K3: final cost --------------------------------------------
__global__ void k_final(const float* __restrict__ pb, const float* __restrict__ tb,
                        float* __restrict__ out) {
    int idx = blockIdx.x * 256 + threadIdx.x;
    if (idx >= BB*NQ*NT) return;
    int t = idx % NT; int r = idx / NT; int q = r % NQ; int b = r / NQ;

    float c1 = 0.f, c2 = 0.f;
    #pragma unroll
    for (int sk = 0; sk < SPLITK; sk++) {
        size_t off = ((size_t)(sk*BB + b)*NQ + q)*NT + t;
        c1 += g_C1p[off]; c2 += g_C2p[off];
    }
    float neg = 0.f, ss = 0.f;
    #pragma unroll
    for (int k = 0; k < 4; k++) {
        neg += g_negP[k*BB*NQ + b*NQ + q];
        ss  += g_sP  [k*BB*NQ + b*NQ + q];
    }
    float ts  = g_tmsum[b*NT + t];
    float cost_mask = (neg - c1) * (1.0f/(float)NP);
    float cost_dice = 1.f - (2.f*c2 + 1.f) / (ss + ts + 1.f);

    float4 pbox = ((const float4*)pb)[(size_t)b*NQ + q];
    float4 tbox = ((const float4*)tb)[(size_t)b*NT + t];
    float l1 = fabsf(pbox.x - tbox.x) + fabsf(pbox.y - tbox.y)
             + fabsf(pbox.z - tbox.z) + fabsf(pbox.w - tbox.w);

    float ax0 = pbox.x - 0.5f*pbox.z, ay0 = pbox.y - 0.5f*pbox.w;
    float ax1 = pbox.x + 0.5f*pbox.z, ay1 = pbox.y + 0.5f*pbox.w;
    float bx0 = tbox.x - 0.5f*tbox.z, by0 = tbox.y - 0.5f*tbox.w;
    float bx1 = tbox.x + 0.5f*tbox.z, by1 = tbox.y + 0.5f*tbox.w;
    float areaA = (ax1 - ax0)*(ay1 - ay0);
    float areaB = (bx1 - bx0)*(by1 - by0);
    float iw = fmaxf(fminf(ax1, bx1) - fmaxf(ax0, bx0), 0.f);
    float ih = fmaxf(fminf(ay1, by1) - fmaxf(ay0, by0), 0.f);
    float inter = iw * ih;
    float uni = areaA + areaB - inter;
    float iou = inter / uni;
    float ew = fmaxf(fmaxf(ax1, bx1) - fminf(ax0, bx0), 0.f);
    float eh = fmaxf(fmaxf(ay1, by1) - fminf(ay0, by0), 0.f);
    float areaE = ew * eh;
    float giou = iou - (areaE - uni) / areaE;

    out[idx] = 5.f*cost_mask + 5.f*cost_dice + 5.f*l1 - 2.f*giou;
}

// ---------------- launch ------------------------------------------------------
extern "C" void kernel_launch(void* const* d_in, const int* in_sizes, int n_in,
                              void* d_out, int out_size) {
    const float* pred_masks = (const float*)d_in[0];
    const float* tgt_masks  = (const float*)d_in[1];
    const float* pred_boxes = (const float*)d_in[2];
    const float* tgt_boxes  = (const float*)d_in[3];
    const float* pts        = (const float*)d_in[4];
    float* out = (float*)d_out;

    static cudaStream_t side = []() {
        cudaStream_t s; cudaStreamCreateWithFlags(&s, cudaStreamNonBlocking); return s;
    }();
    static cudaEvent_t evFork = []() { cudaEvent_t e; cudaEventCreateWithFlags(&e, cudaEventDisableTiming); return e; }();
    static cudaEvent_t evJoin = []() { cudaEvent_t e; cudaEventCreateWithFlags(&e, cudaEventDisableTiming); return e; }();

    k_build<<<BB, 1024>>>(pts);
    cudaEventRecord(evFork, 0);
    cudaStreamWaitEvent(side, evFork, 0);

    k_sample_tgt <<<dim3(NT, BB), 512, 0, side>>>(tgt_masks);
    k_sample_pred<<<dim3(NQ, BB, 4), 512>>>(pred_masks);
    cudaEventRecord(evJoin, side);
    cudaStreamWaitEvent(0, evJoin, 0);

    k_gemm<<<dim3(5, 5, BB*SPLITK), 128>>>();
    k_final<<<(BB*NQ*NT + 255)/256, 256>>>(pred_boxes, tgt_boxes, out);
}